// round 16
// baseline (speedup 1.0000x reference)
#include <cuda_runtime.h>
#include <cuda_fp16.h>
#include <cstdint>

#define NB 16
#define NC 128
#define NN 4096
#define NGROUPS 8
#define CPG 16
#define LOG2E 1.4426950408889634f

// ---------------- scratch ----------------
__device__ float  g_mean[NB * NGROUPS];
__device__ float  g_rstd[NB * NGROUPS];
__device__ float2 g_part[NB * NGROUPS * 4];
__device__ __half g_q[(size_t)NB * NC * NN];
__device__ __half g_k[(size_t)NB * NC * NN];
__device__ __half g_v[(size_t)NB * NC * NN];

// ---------------- helpers ----------------
__device__ __forceinline__ uint32_t sptr(const void* p) {
    return (uint32_t)__cvta_generic_to_shared(p);
}
__device__ __forceinline__ void ldm_x4(uint32_t* r, uint32_t a) {
    asm volatile("ldmatrix.sync.aligned.m8n8.x4.shared.b16 {%0,%1,%2,%3}, [%4];"
                 : "=r"(r[0]), "=r"(r[1]), "=r"(r[2]), "=r"(r[3]) : "r"(a));
}
__device__ __forceinline__ void ldm_x4_t(uint32_t* r, uint32_t a) {
    asm volatile("ldmatrix.sync.aligned.m8n8.x4.trans.shared.b16 {%0,%1,%2,%3}, [%4];"
                 : "=r"(r[0]), "=r"(r[1]), "=r"(r[2]), "=r"(r[3]) : "r"(a));
}
__device__ __forceinline__ void mma16816(float* c, const uint32_t* a, const uint32_t* b) {
    asm volatile("mma.sync.aligned.m16n8k16.row.col.f32.f16.f16.f32 "
                 "{%0,%1,%2,%3}, {%4,%5,%6,%7}, {%8,%9}, {%0,%1,%2,%3};"
                 : "+f"(c[0]), "+f"(c[1]), "+f"(c[2]), "+f"(c[3])
                 : "r"(a[0]), "r"(a[1]), "r"(a[2]), "r"(a[3]), "r"(b[0]), "r"(b[1]));
}
__device__ __forceinline__ float ex2f(float x) {
    float y; asm("ex2.approx.f32 %0, %1;" : "=f"(y) : "f"(x)); return y;
}
__device__ __forceinline__ uint32_t exp2pack(float lo, float hi) {
    uint32_t h, r;
    asm("cvt.rn.f16x2.f32 %0, %1, %2;" : "=r"(h) : "f"(hi), "f"(lo));
    asm("ex2.approx.f16x2 %0, %1;" : "=r"(r) : "r"(h));
    return r;
}
__device__ __forceinline__ uint32_t packh2(float a, float b) {
    __half2 h = __floats2half2_rn(a, b);
    return *reinterpret_cast<uint32_t*>(&h);
}
__device__ __forceinline__ void cpa16(void* dst, const void* src) {
    asm volatile("cp.async.cg.shared.global [%0], [%1], 16;\n"
                 :: "r"(sptr(dst)), "l"(src));
}
#define CP_COMMIT() asm volatile("cp.async.commit_group;")

// ---------------- kernel 1a: groupnorm partial sums ----------------
__global__ void gn_part_kernel(const float* __restrict__ x) {
    int blk = blockIdx.x;
    const float* xp = x + (size_t)(blk >> 2) * (CPG * NN) + (blk & 3) * 16384;
    float s = 0.f, ss = 0.f;
    for (int i = threadIdx.x * 4; i < 16384; i += 256 * 4) {
        float4 v = *(const float4*)(xp + i);
        s  += (v.x + v.y) + (v.z + v.w);
        ss += v.x * v.x + v.y * v.y + v.z * v.z + v.w * v.w;
    }
#pragma unroll
    for (int o = 16; o; o >>= 1) {
        s  += __shfl_xor_sync(~0u, s, o);
        ss += __shfl_xor_sync(~0u, ss, o);
    }
    __shared__ float red[16];
    int warp = threadIdx.x >> 5;
    if ((threadIdx.x & 31) == 0) { red[warp] = s; red[8 + warp] = ss; }
    __syncthreads();
    if (threadIdx.x == 0) {
        float S = 0.f, SS = 0.f;
        for (int i = 0; i < 8; i++) { S += red[i]; SS += red[8 + i]; }
        g_part[blk] = make_float2(S, SS);
    }
}

// ---------------- kernel 1b: finalize ----------------
__global__ void gn_fin_kernel() {
    int bg = threadIdx.x;
    float s = 0.f, ss = 0.f;
#pragma unroll
    for (int j = 0; j < 4; j++) {
        float2 p = g_part[bg * 4 + j];
        s += p.x; ss += p.y;
    }
    float inv = 1.f / (float)(CPG * NN);
    float mean = s * inv;
    float var  = ss * inv - mean * mean;
    g_mean[bg] = mean;
    g_rstd[bg] = rsqrtf(var + 1e-5f);
}

// ---------------- kernel 2: GN apply + QKV projection (2 CTAs/SM) ----------------
__global__ __launch_bounds__(256, 2) void qkv_kernel(
    const float* __restrict__ x, const float* __restrict__ gnw, const float* __restrict__ gnb,
    const float* __restrict__ wq, const float* __restrict__ bq,
    const float* __restrict__ wk, const float* __restrict__ bk,
    const float* __restrict__ wv, const float* __restrict__ bv)
{
    __shared__ __half xs[128][136];
    int b = blockIdx.y, p0 = blockIdx.x * 128;
    int tid = threadIdx.x;
    const float* xb = x + (size_t)b * NC * NN;

    for (int idx = tid; idx < 128 * 32; idx += 256) {
        int c = idx >> 5, u = idx & 31;
        float4 v = *(const float4*)(xb + (size_t)c * NN + p0 + u * 4);
        float rstd = g_rstd[b * NGROUPS + (c >> 4)];
        float mean = g_mean[b * NGROUPS + (c >> 4)];
        float ga = gnw[c] * rstd;
        float be = gnb[c] - mean * ga;
        __half2* d = (__half2*)&xs[c][u * 4];
        d[0] = __floats2half2_rn(v.x * ga + be, v.y * ga + be);
        d[1] = __floats2half2_rn(v.z * ga + be, v.w * ga + be);
    }
    __syncthreads();

    int warp = tid >> 5, lane = tid & 31;
    int oc0 = warp * 16;
    int rr = lane >> 2, c2 = (lane & 3) * 2;
    int browoff = (lane & 7) + 8 * ((lane >> 3) & 1);
    int bcol = 8 * (lane >> 4);

    const float* Ws[3] = {wq, wk, wv};
    const float* Bi[3] = {bq, bk, bv};
    __half* Out[3] = {g_q + (size_t)b * NC * NN, g_k + (size_t)b * NC * NN, g_v + (size_t)b * NC * NN};
    const float qscale = 0.08838834764831845f * LOG2E;

    for (int m = 0; m < 3; m++) {
        const float* W = Ws[m];
        uint32_t A[8][4];
#pragma unroll
        for (int kb = 0; kb < 8; kb++) {
            int cc = kb * 16 + c2;
            float2 x0 = *(const float2*)(W + (size_t)(oc0 + rr) * NC + cc);
            float2 x1 = *(const float2*)(W + (size_t)(oc0 + rr + 8) * NC + cc);
            float2 x2 = *(const float2*)(W + (size_t)(oc0 + rr) * NC + cc + 8);
            float2 x3 = *(const float2*)(W + (size_t)(oc0 + rr + 8) * NC + cc + 8);
            A[kb][0] = packh2(x0.x, x0.y); A[kb][1] = packh2(x1.x, x1.y);
            A[kb][2] = packh2(x2.x, x2.y); A[kb][3] = packh2(x3.x, x3.y);
        }
        float br  = Bi[m][oc0 + rr];
        float br8 = Bi[m][oc0 + rr + 8];
        float sc = (m == 0) ? qscale : 1.f;
        __half* out = Out[m];
#pragma unroll
        for (int pp = 0; pp < 8; pp++) {
            float acc[8] = {0.f, 0.f, 0.f, 0.f, 0.f, 0.f, 0.f, 0.f};
#pragma unroll
            for (int kb = 0; kb < 8; kb++) {
                uint32_t bfr[4];
                ldm_x4_t(bfr, sptr(&xs[kb * 16 + browoff][pp * 16 + bcol]));
                mma16816(acc,     A[kb], bfr);
                mma16816(acc + 4, A[kb], bfr + 2);
            }
            int pc = p0 + pp * 16 + c2;
            *(__half2*)(out + (size_t)(oc0 + rr) * NN + pc)         = __floats2half2_rn((acc[0] + br) * sc, (acc[1] + br) * sc);
            *(__half2*)(out + (size_t)(oc0 + rr + 8) * NN + pc)     = __floats2half2_rn((acc[2] + br8) * sc, (acc[3] + br8) * sc);
            *(__half2*)(out + (size_t)(oc0 + rr) * NN + pc + 8)     = __floats2half2_rn((acc[4] + br) * sc, (acc[5] + br) * sc);
            *(__half2*)(out + (size_t)(oc0 + rr + 8) * NN + pc + 8) = __floats2half2_rn((acc[6] + br8) * sc, (acc[7] + br8) * sc);
        }
    }
}

// ---------------- kernel 3: flash attention BM=64 (2 CTAs/SM) + fused proj ----------------
#define STAGE_H (2 * 128 * 72)               // halves per stage (K[128][72] + V[128][72])
#define ATTN_SMEM (3 * STAGE_H * 2)          // 110592 bytes per CTA

__global__ __launch_bounds__(128, 2) void attn_kernel(
    const float* __restrict__ x, const float* __restrict__ wf,
    const float* __restrict__ bf, float* __restrict__ out)
{
    extern __shared__ __half dyn[];
    __shared__ float bfs[128];

    int b = blockIdx.y, i0 = blockIdx.x * 64;
    int tid = threadIdx.x, warp = tid >> 5, lane = tid & 31;
    size_t off = (size_t)b * NC * NN;

    // ---- stage Q tile [128 d][64 pos] (pad 72); build A-frags ----
    {
        __half (*Qs)[72] = (__half(*)[72])dyn;
        const __half* qp = g_q + off + i0;
        for (int idx = tid; idx < 1024; idx += 128) {
            int d = idx >> 3, u = idx & 7;
            *(uint4*)&Qs[d][u * 8] = *(const uint4*)(qp + (size_t)d * NN + u * 8);
        }
    }
    __syncthreads();
    uint32_t QA[8][4];
    {
        __half (*Qs)[72] = (__half(*)[72])dyn;
        int r  = 8 * (lane >> 4) + (lane & 7);
        int cq = warp * 16 + 8 * ((lane >> 3) & 1);
#pragma unroll
        for (int kb = 0; kb < 8; kb++)
            ldm_x4_t(QA[kb], sptr(&Qs[kb * 16 + r][cq]));
    }
    __syncthreads();

    // ---- prologue: prefetch tiles 0,1,2 ----
    {
        const __half* kb0 = g_k + off;
        const __half* vb0 = g_v + off;
#pragma unroll
        for (int s = 0; s < 3; s++) {
            __half* ks = dyn + s * STAGE_H;
            __half* vs = ks + 128 * 72;
            const __half* kp = kb0 + s * 64;
            const __half* vp = vb0 + s * 64;
#pragma unroll
            for (int it = 0; it < 8; it++) {
                int i = tid + it * 128;
                int c = i >> 3, u = i & 7;
                cpa16(ks + c * 72 + u * 8, kp + (size_t)c * NN + u * 8);
                cpa16(vs + c * 72 + u * 8, vp + (size_t)c * NN + u * 8);
            }
            CP_COMMIT();
        }
    }

    float O[16][4];
#pragma unroll
    for (int i = 0; i < 16; i++) { O[i][0] = O[i][1] = O[i][2] = O[i][3] = 0.f; }
    float m0 = -1e30f, m1 = -1e30f;
    float l0 = 0.f, l1 = 0.f;   // per-lane partials; quad-reduced once at end

    int krow = (lane & 7) + 8 * ((lane >> 3) & 1);
    int kcol = 8 * (lane >> 4);
    int vrow = 8 * (lane >> 4) + (lane & 7);
    int vcol = 8 * ((lane >> 3) & 1);

    for (int jb = 0; jb < 64; jb++) {
        if (jb <= 61)      asm volatile("cp.async.wait_group 2;");
        else if (jb == 62) asm volatile("cp.async.wait_group 1;");
        else               asm volatile("cp.async.wait_group 0;");
        __syncthreads();

        int st = jb % 3;
        __half (*Ks)[72] = (__half(*)[72])(dyn + st * STAGE_H);
        __half (*Vs)[72] = (__half(*)[72])(dyn + st * STAGE_H + 128 * 72);

        // S = Q K^T (log2-scaled already)
        float S[8][4];
#pragma unroll
        for (int jp = 0; jp < 4; jp++) {
            float* s0 = S[2 * jp];
            float* s1 = S[2 * jp + 1];
            s0[0] = s0[1] = s0[2] = s0[3] = 0.f;
            s1[0] = s1[1] = s1[2] = s1[3] = 0.f;
#pragma unroll
            for (int kb = 0; kb < 8; kb++) {
                uint32_t bfr[4];
                ldm_x4_t(bfr, sptr(&Ks[kb * 16 + krow][jp * 16 + kcol]));
                mma16816(s0, QA[kb], bfr);
                mma16816(s1, QA[kb], bfr + 2);
            }
        }

        // online softmax (max via 2 shuffles; l sums kept per-lane, reduced at end)
        float r0 = S[0][0], r1 = S[0][2];
#pragma unroll
        for (int t = 0; t < 8; t++) {
            r0 = fmaxf(r0, fmaxf(S[t][0], S[t][1]));
            r1 = fmaxf(r1, fmaxf(S[t][2], S[t][3]));
        }
        r0 = fmaxf(r0, __shfl_xor_sync(~0u, r0, 1)); r0 = fmaxf(r0, __shfl_xor_sync(~0u, r0, 2));
        r1 = fmaxf(r1, __shfl_xor_sync(~0u, r1, 1)); r1 = fmaxf(r1, __shfl_xor_sync(~0u, r1, 2));

        bool up = (r0 > m0) || (r1 > m1);
        float nm0 = m0, nm1 = m1;
        if (__any_sync(~0u, up)) {
            nm0 = fmaxf(m0, r0); nm1 = fmaxf(m1, r1);
            float a0 = ex2f(m0 - nm0), a1 = ex2f(m1 - nm1);
            l0 *= a0; l1 *= a1;
#pragma unroll
            for (int t = 0; t < 16; t++) { O[t][0] *= a0; O[t][1] *= a0; O[t][2] *= a1; O[t][3] *= a1; }
            m0 = nm0; m1 = nm1;
        }

        uint32_t PA[4][4];
        __half2 hs0 = __floats2half2_rn(0.f, 0.f), hs1 = hs0;
#pragma unroll
        for (int j = 0; j < 4; j++) {
            PA[j][0] = exp2pack(S[2*j][0]   - nm0, S[2*j][1]   - nm0);
            PA[j][1] = exp2pack(S[2*j][2]   - nm1, S[2*j][3]   - nm1);
            PA[j][2] = exp2pack(S[2*j+1][0] - nm0, S[2*j+1][1] - nm0);
            PA[j][3] = exp2pack(S[2*j+1][2] - nm1, S[2*j+1][3] - nm1);
            hs0 = __hadd2(hs0, __hadd2(*(__half2*)&PA[j][0], *(__half2*)&PA[j][2]));
            hs1 = __hadd2(hs1, __hadd2(*(__half2*)&PA[j][1], *(__half2*)&PA[j][3]));
        }
        l0 += __low2float(hs0) + __high2float(hs0);   // per-lane partial (16 of 64 cols)
        l1 += __low2float(hs1) + __high2float(hs1);

        // O += P V
#pragma unroll
        for (int cp = 0; cp < 8; cp++) {
#pragma unroll
            for (int j = 0; j < 4; j++) {
                uint32_t bfr[4];
                ldm_x4(bfr, sptr(&Vs[cp * 16 + vrow][j * 16 + vcol]));
                mma16816(O[2 * cp],     PA[j], bfr);
                mma16816(O[2 * cp + 1], PA[j], bfr + 2);
            }
        }
        __syncthreads();

        if (jb + 3 < 64) {
            __half* ks = dyn + st * STAGE_H;
            __half* vs = ks + 128 * 72;
            const __half* kp = g_k + off + (jb + 3) * 64;
            const __half* vp = g_v + off + (jb + 3) * 64;
#pragma unroll
            for (int it = 0; it < 8; it++) {
                int i = tid + it * 128;
                int c = i >> 3, u = i & 7;
                cpa16(ks + c * 72 + u * 8, kp + (size_t)c * NN + u * 8);
                cpa16(vs + c * 72 + u * 8, vp + (size_t)c * NN + u * 8);
            }
        }
        CP_COMMIT();
    }

    // deferred quad reduction of l
    l0 += __shfl_xor_sync(~0u, l0, 1); l0 += __shfl_xor_sync(~0u, l0, 2);
    l1 += __shfl_xor_sync(~0u, l1, 1); l1 += __shfl_xor_sync(~0u, l1, 2);

    // ================= fused output projection epilogue =================
    __syncthreads();
    {
        __half (*wfs)[136] = (__half(*)[136])dyn;
        for (int idx = tid; idx < 128 * 32; idx += 128) {
            int oc = idx >> 5, u = idx & 31;
            float4 v = *(const float4*)(wf + (size_t)oc * NC + u * 4);
            __half2* d = (__half2*)&wfs[oc][u * 4];
            d[0] = __floats2half2_rn(v.x, v.y);
            d[1] = __floats2half2_rn(v.z, v.w);
        }
        if (tid < 128) bfs[tid] = bf[tid];
    }

    // pack normalized o into A-frags (rows = position, k = channel)
    float il0 = 1.f / l0, il1 = 1.f / l1;
    uint32_t AN[8][4];
#pragma unroll
    for (int kb = 0; kb < 8; kb++) {
        AN[kb][0] = packh2(O[2*kb][0]   * il0, O[2*kb][1]   * il0);
        AN[kb][1] = packh2(O[2*kb][2]   * il1, O[2*kb][3]   * il1);
        AN[kb][2] = packh2(O[2*kb+1][0] * il0, O[2*kb+1][1] * il0);
        AN[kb][3] = packh2(O[2*kb+1][2] * il1, O[2*kb+1][3] * il1);
    }
    __syncthreads();

    // R[pos][oc] = o_norm x wf^T
    {
        __half (*wfs)[136] = (__half(*)[136])dyn;
        float R[16][4];
#pragma unroll
        for (int i = 0; i < 16; i++) { R[i][0] = R[i][1] = R[i][2] = R[i][3] = 0.f; }
#pragma unroll
        for (int ob = 0; ob < 8; ob++) {
#pragma unroll
            for (int kb = 0; kb < 8; kb++) {
                uint32_t bfr[4];
                ldm_x4(bfr, sptr(&wfs[ob * 16 + vrow][kb * 16 + vcol]));
                mma16816(R[2 * ob],     AN[kb], bfr);
                mma16816(R[2 * ob + 1], AN[kb], bfr + 2);
            }
        }

        // out[oc][pos] = R + bias + x (residual)
        int row = i0 + warp * 16 + (lane >> 2);
        int c2 = (lane & 3) * 2;
        const float* xb = x + off;
        float* ob2 = out + off;
#pragma unroll
        for (int t = 0; t < 16; t++) {
            int oc = t * 8 + c2;
            size_t a0i = (size_t)oc * NN + row;
            size_t a1i = (size_t)(oc + 1) * NN + row;
            float b0 = bfs[oc], b1 = bfs[oc + 1];
            ob2[a0i]     = R[t][0] + b0 + xb[a0i];
            ob2[a1i]     = R[t][1] + b1 + xb[a1i];
            ob2[a0i + 8] = R[t][2] + b0 + xb[a0i + 8];
            ob2[a1i + 8] = R[t][3] + b1 + xb[a1i + 8];
        }
    }
}

// ---------------- launch ----------------
extern "C" void kernel_launch(void* const* d_in, const int* in_sizes, int n_in,
                              void* d_out, int out_size)
{
    (void)in_sizes; (void)n_in; (void)out_size;
    const float* x  = (const float*)d_in[0];
    const float* gw = (const float*)d_in[1];
    const float* gb = (const float*)d_in[2];
    const float* wq = (const float*)d_in[3];
    const float* bq = (const float*)d_in[4];
    const float* wk = (const float*)d_in[5];
    const float* bk = (const float*)d_in[6];
    const float* wv = (const float*)d_in[7];
    const float* bv = (const float*)d_in[8];
    const float* wf = (const float*)d_in[9];
    const float* bf = (const float*)d_in[10];
    float* out = (float*)d_out;

    static_assert(ATTN_SMEM == 110592, "smem size");
    cudaFuncSetAttribute(attn_kernel, cudaFuncAttributeMaxDynamicSharedMemorySize, ATTN_SMEM);

    gn_part_kernel<<<NB * NGROUPS * 4, 256>>>(x);
    gn_fin_kernel<<<1, 128>>>();
    qkv_kernel<<<dim3(32, NB), 256>>>(x, gw, gb, wq, bq, wk, bk, wv, bv);
    attn_kernel<<<dim3(64, NB), 128, ATTN_SMEM>>>(x, wf, bf, out);
}

// round 17
// speedup vs baseline: 1.0605x; 1.0605x over previous
#include <cuda_runtime.h>
#include <cuda_fp16.h>
#include <cstdint>

#define NB 16
#define NC 128
#define NN 4096
#define NGROUPS 8
#define CPG 16
#define LOG2E 1.4426950408889634f

// ---------------- scratch ----------------
__device__ float  g_mean[NB * NGROUPS];
__device__ float  g_rstd[NB * NGROUPS];
__device__ float2 g_part[NB * NGROUPS * 4];
__device__ __half g_q[(size_t)NB * NC * NN];
__device__ __half g_k[(size_t)NB * NC * NN];
__device__ __half g_v[(size_t)NB * NC * NN];

// ---------------- helpers ----------------
__device__ __forceinline__ uint32_t sptr(const void* p) {
    return (uint32_t)__cvta_generic_to_shared(p);
}
__device__ __forceinline__ void ldm_x4(uint32_t* r, uint32_t a) {
    asm volatile("ldmatrix.sync.aligned.m8n8.x4.shared.b16 {%0,%1,%2,%3}, [%4];"
                 : "=r"(r[0]), "=r"(r[1]), "=r"(r[2]), "=r"(r[3]) : "r"(a));
}
__device__ __forceinline__ void ldm_x4_t(uint32_t* r, uint32_t a) {
    asm volatile("ldmatrix.sync.aligned.m8n8.x4.trans.shared.b16 {%0,%1,%2,%3}, [%4];"
                 : "=r"(r[0]), "=r"(r[1]), "=r"(r[2]), "=r"(r[3]) : "r"(a));
}
__device__ __forceinline__ void mma16816(float* c, const uint32_t* a, const uint32_t* b) {
    asm volatile("mma.sync.aligned.m16n8k16.row.col.f32.f16.f16.f32 "
                 "{%0,%1,%2,%3}, {%4,%5,%6,%7}, {%8,%9}, {%0,%1,%2,%3};"
                 : "+f"(c[0]), "+f"(c[1]), "+f"(c[2]), "+f"(c[3])
                 : "r"(a[0]), "r"(a[1]), "r"(a[2]), "r"(a[3]), "r"(b[0]), "r"(b[1]));
}
__device__ __forceinline__ float ex2f(float x) {
    float y; asm("ex2.approx.f32 %0, %1;" : "=f"(y) : "f"(x)); return y;
}
__device__ __forceinline__ uint32_t exp2pack(float lo, float hi) {
    uint32_t h, r;
    asm("cvt.rn.f16x2.f32 %0, %1, %2;" : "=r"(h) : "f"(hi), "f"(lo));
    asm("ex2.approx.f16x2 %0, %1;" : "=r"(r) : "r"(h));
    return r;
}
__device__ __forceinline__ uint32_t packh2(float a, float b) {
    __half2 h = __floats2half2_rn(a, b);
    return *reinterpret_cast<uint32_t*>(&h);
}
__device__ __forceinline__ void cpa16(void* dst, const void* src) {
    asm volatile("cp.async.cg.shared.global [%0], [%1], 16;\n"
                 :: "r"(sptr(dst)), "l"(src));
}
#define CP_COMMIT() asm volatile("cp.async.commit_group;")

// ---------------- kernel 1a: groupnorm partial sums ----------------
__global__ void gn_part_kernel(const float* __restrict__ x) {
    int blk = blockIdx.x;
    const float* xp = x + (size_t)(blk >> 2) * (CPG * NN) + (blk & 3) * 16384;
    float s = 0.f, ss = 0.f;
    for (int i = threadIdx.x * 4; i < 16384; i += 256 * 4) {
        float4 v = *(const float4*)(xp + i);
        s  += (v.x + v.y) + (v.z + v.w);
        ss += v.x * v.x + v.y * v.y + v.z * v.z + v.w * v.w;
    }
#pragma unroll
    for (int o = 16; o; o >>= 1) {
        s  += __shfl_xor_sync(~0u, s, o);
        ss += __shfl_xor_sync(~0u, ss, o);
    }
    __shared__ float red[16];
    int warp = threadIdx.x >> 5;
    if ((threadIdx.x & 31) == 0) { red[warp] = s; red[8 + warp] = ss; }
    __syncthreads();
    if (threadIdx.x == 0) {
        float S = 0.f, SS = 0.f;
        for (int i = 0; i < 8; i++) { S += red[i]; SS += red[8 + i]; }
        g_part[blk] = make_float2(S, SS);
    }
}

// ---------------- kernel 1b: finalize ----------------
__global__ void gn_fin_kernel() {
    int bg = threadIdx.x;
    float s = 0.f, ss = 0.f;
#pragma unroll
    for (int j = 0; j < 4; j++) {
        float2 p = g_part[bg * 4 + j];
        s += p.x; ss += p.y;
    }
    float inv = 1.f / (float)(CPG * NN);
    float mean = s * inv;
    float var  = ss * inv - mean * mean;
    g_mean[bg] = mean;
    g_rstd[bg] = rsqrtf(var + 1e-5f);
}

// ---------------- kernel 2: GN apply + QKV projection ----------------
__global__ __launch_bounds__(256, 1) void qkv_kernel(
    const float* __restrict__ x, const float* __restrict__ gnw, const float* __restrict__ gnb,
    const float* __restrict__ wq, const float* __restrict__ bq,
    const float* __restrict__ wk, const float* __restrict__ bk,
    const float* __restrict__ wv, const float* __restrict__ bv)
{
    __shared__ __half xs[128][136];
    int b = blockIdx.y, p0 = blockIdx.x * 128;
    int tid = threadIdx.x;
    const float* xb = x + (size_t)b * NC * NN;

    for (int idx = tid; idx < 128 * 32; idx += 256) {
        int c = idx >> 5, u = idx & 31;
        float4 v = *(const float4*)(xb + (size_t)c * NN + p0 + u * 4);
        float rstd = g_rstd[b * NGROUPS + (c >> 4)];
        float mean = g_mean[b * NGROUPS + (c >> 4)];
        float ga = gnw[c] * rstd;
        float be = gnb[c] - mean * ga;
        __half2* d = (__half2*)&xs[c][u * 4];
        d[0] = __floats2half2_rn(v.x * ga + be, v.y * ga + be);
        d[1] = __floats2half2_rn(v.z * ga + be, v.w * ga + be);
    }
    __syncthreads();

    int warp = tid >> 5, lane = tid & 31;
    int oc0 = warp * 16;
    int rr = lane >> 2, c2 = (lane & 3) * 2;
    int browoff = (lane & 7) + 8 * ((lane >> 3) & 1);
    int bcol = 8 * (lane >> 4);

    const float* Ws[3] = {wq, wk, wv};
    const float* Bi[3] = {bq, bk, bv};
    __half* Out[3] = {g_q + (size_t)b * NC * NN, g_k + (size_t)b * NC * NN, g_v + (size_t)b * NC * NN};
    const float qscale = 0.08838834764831845f * LOG2E;

    for (int m = 0; m < 3; m++) {
        const float* W = Ws[m];
        uint32_t A[8][4];
#pragma unroll
        for (int kb = 0; kb < 8; kb++) {
            int cc = kb * 16 + c2;
            float2 x0 = *(const float2*)(W + (size_t)(oc0 + rr) * NC + cc);
            float2 x1 = *(const float2*)(W + (size_t)(oc0 + rr + 8) * NC + cc);
            float2 x2 = *(const float2*)(W + (size_t)(oc0 + rr) * NC + cc + 8);
            float2 x3 = *(const float2*)(W + (size_t)(oc0 + rr + 8) * NC + cc + 8);
            A[kb][0] = packh2(x0.x, x0.y); A[kb][1] = packh2(x1.x, x1.y);
            A[kb][2] = packh2(x2.x, x2.y); A[kb][3] = packh2(x3.x, x3.y);
        }
        float br  = Bi[m][oc0 + rr];
        float br8 = Bi[m][oc0 + rr + 8];
        float sc = (m == 0) ? qscale : 1.f;
        __half* out = Out[m];
#pragma unroll
        for (int pp = 0; pp < 8; pp++) {
            float acc[8] = {0.f, 0.f, 0.f, 0.f, 0.f, 0.f, 0.f, 0.f};
#pragma unroll
            for (int kb = 0; kb < 8; kb++) {
                uint32_t bfr[4];
                ldm_x4_t(bfr, sptr(&xs[kb * 16 + browoff][pp * 16 + bcol]));
                mma16816(acc,     A[kb], bfr);
                mma16816(acc + 4, A[kb], bfr + 2);
            }
            int pc = p0 + pp * 16 + c2;
            *(__half2*)(out + (size_t)(oc0 + rr) * NN + pc)         = __floats2half2_rn((acc[0] + br) * sc, (acc[1] + br) * sc);
            *(__half2*)(out + (size_t)(oc0 + rr + 8) * NN + pc)     = __floats2half2_rn((acc[2] + br8) * sc, (acc[3] + br8) * sc);
            *(__half2*)(out + (size_t)(oc0 + rr) * NN + pc + 8)     = __floats2half2_rn((acc[4] + br) * sc, (acc[5] + br) * sc);
            *(__half2*)(out + (size_t)(oc0 + rr + 8) * NN + pc + 8) = __floats2half2_rn((acc[6] + br8) * sc, (acc[7] + br8) * sc);
        }
    }
}

// ---------------- kernel 3: flash attention BM=64 (2 CTAs/SM) + fused proj ----------------
#define STAGE_H (2 * 128 * 72)               // halves per stage (K[128][72] + V[128][72])
#define ATTN_SMEM (3 * STAGE_H * 2)          // 110592 bytes per CTA

__global__ __launch_bounds__(128, 2) void attn_kernel(
    const float* __restrict__ x, const float* __restrict__ wf,
    const float* __restrict__ bf, float* __restrict__ out)
{
    extern __shared__ __half dyn[];
    __shared__ float bfs[128];

    int b = blockIdx.y, i0 = blockIdx.x * 64;
    int tid = threadIdx.x, warp = tid >> 5, lane = tid & 31;
    size_t off = (size_t)b * NC * NN;

    // ---- stage Q tile [128 d][64 pos] (pad 72); build A-frags ----
    {
        __half (*Qs)[72] = (__half(*)[72])dyn;
        const __half* qp = g_q + off + i0;
        for (int idx = tid; idx < 1024; idx += 128) {
            int d = idx >> 3, u = idx & 7;
            *(uint4*)&Qs[d][u * 8] = *(const uint4*)(qp + (size_t)d * NN + u * 8);
        }
    }
    __syncthreads();
    uint32_t QA[8][4];
    {
        __half (*Qs)[72] = (__half(*)[72])dyn;
        int r  = 8 * (lane >> 4) + (lane & 7);
        int cq = warp * 16 + 8 * ((lane >> 3) & 1);
#pragma unroll
        for (int kb = 0; kb < 8; kb++)
            ldm_x4_t(QA[kb], sptr(&Qs[kb * 16 + r][cq]));
    }
    __syncthreads();

    // ---- prologue: prefetch tiles 0,1,2 ----
    {
        const __half* kb0 = g_k + off;
        const __half* vb0 = g_v + off;
#pragma unroll
        for (int s = 0; s < 3; s++) {
            __half* ks = dyn + s * STAGE_H;
            __half* vs = ks + 128 * 72;
            const __half* kp = kb0 + s * 64;
            const __half* vp = vb0 + s * 64;
#pragma unroll
            for (int it = 0; it < 8; it++) {
                int i = tid + it * 128;
                int c = i >> 3, u = i & 7;
                cpa16(ks + c * 72 + u * 8, kp + (size_t)c * NN + u * 8);
                cpa16(vs + c * 72 + u * 8, vp + (size_t)c * NN + u * 8);
            }
            CP_COMMIT();
        }
    }

    float O[16][4];
#pragma unroll
    for (int i = 0; i < 16; i++) { O[i][0] = O[i][1] = O[i][2] = O[i][3] = 0.f; }
    float m0 = -1e30f, m1 = -1e30f;
    float l0 = 0.f, l1 = 0.f;   // per-lane partials; quad-reduced once at end

    int krow = (lane & 7) + 8 * ((lane >> 3) & 1);
    int kcol = 8 * (lane >> 4);
    int vrow = 8 * (lane >> 4) + (lane & 7);
    int vcol = 8 * ((lane >> 3) & 1);

    for (int jb = 0; jb < 64; jb++) {
        if (jb <= 61)      asm volatile("cp.async.wait_group 2;");
        else if (jb == 62) asm volatile("cp.async.wait_group 1;");
        else               asm volatile("cp.async.wait_group 0;");
        __syncthreads();

        int st = jb % 3;
        __half (*Ks)[72] = (__half(*)[72])(dyn + st * STAGE_H);
        __half (*Vs)[72] = (__half(*)[72])(dyn + st * STAGE_H + 128 * 72);

        // S = Q K^T (log2-scaled already)
        float S[8][4];
#pragma unroll
        for (int jp = 0; jp < 4; jp++) {
            float* s0 = S[2 * jp];
            float* s1 = S[2 * jp + 1];
            s0[0] = s0[1] = s0[2] = s0[3] = 0.f;
            s1[0] = s1[1] = s1[2] = s1[3] = 0.f;
#pragma unroll
            for (int kb = 0; kb < 8; kb++) {
                uint32_t bfr[4];
                ldm_x4_t(bfr, sptr(&Ks[kb * 16 + krow][jp * 16 + kcol]));
                mma16816(s0, QA[kb], bfr);
                mma16816(s1, QA[kb], bfr + 2);
            }
        }

        // online softmax (max via 2 shuffles; l sums kept per-lane, reduced at end)
        float r0 = S[0][0], r1 = S[0][2];
#pragma unroll
        for (int t = 0; t < 8; t++) {
            r0 = fmaxf(r0, fmaxf(S[t][0], S[t][1]));
            r1 = fmaxf(r1, fmaxf(S[t][2], S[t][3]));
        }
        r0 = fmaxf(r0, __shfl_xor_sync(~0u, r0, 1)); r0 = fmaxf(r0, __shfl_xor_sync(~0u, r0, 2));
        r1 = fmaxf(r1, __shfl_xor_sync(~0u, r1, 1)); r1 = fmaxf(r1, __shfl_xor_sync(~0u, r1, 2));

        bool up = (r0 > m0) || (r1 > m1);
        float nm0 = m0, nm1 = m1;
        if (__any_sync(~0u, up)) {
            nm0 = fmaxf(m0, r0); nm1 = fmaxf(m1, r1);
            float a0 = ex2f(m0 - nm0), a1 = ex2f(m1 - nm1);
            l0 *= a0; l1 *= a1;
#pragma unroll
            for (int t = 0; t < 16; t++) { O[t][0] *= a0; O[t][1] *= a0; O[t][2] *= a1; O[t][3] *= a1; }
            m0 = nm0; m1 = nm1;
        }

        uint32_t PA[4][4];
        __half2 hs0 = __floats2half2_rn(0.f, 0.f), hs1 = hs0;
#pragma unroll
        for (int j = 0; j < 4; j++) {
            PA[j][0] = exp2pack(S[2*j][0]   - nm0, S[2*j][1]   - nm0);
            PA[j][1] = exp2pack(S[2*j][2]   - nm1, S[2*j][3]   - nm1);
            PA[j][2] = exp2pack(S[2*j+1][0] - nm0, S[2*j+1][1] - nm0);
            PA[j][3] = exp2pack(S[2*j+1][2] - nm1, S[2*j+1][3] - nm1);
            hs0 = __hadd2(hs0, __hadd2(*(__half2*)&PA[j][0], *(__half2*)&PA[j][2]));
            hs1 = __hadd2(hs1, __hadd2(*(__half2*)&PA[j][1], *(__half2*)&PA[j][3]));
        }
        l0 += __low2float(hs0) + __high2float(hs0);   // per-lane partial (16 of 64 cols)
        l1 += __low2float(hs1) + __high2float(hs1);

        // O += P V
#pragma unroll
        for (int cp = 0; cp < 8; cp++) {
#pragma unroll
            for (int j = 0; j < 4; j++) {
                uint32_t bfr[4];
                ldm_x4(bfr, sptr(&Vs[cp * 16 + vrow][j * 16 + vcol]));
                mma16816(O[2 * cp],     PA[j], bfr);
                mma16816(O[2 * cp + 1], PA[j], bfr + 2);
            }
        }
        __syncthreads();

        if (jb + 3 < 64) {
            __half* ks = dyn + st * STAGE_H;
            __half* vs = ks + 128 * 72;
            const __half* kp = g_k + off + (jb + 3) * 64;
            const __half* vp = g_v + off + (jb + 3) * 64;
#pragma unroll
            for (int it = 0; it < 8; it++) {
                int i = tid + it * 128;
                int c = i >> 3, u = i & 7;
                cpa16(ks + c * 72 + u * 8, kp + (size_t)c * NN + u * 8);
                cpa16(vs + c * 72 + u * 8, vp + (size_t)c * NN + u * 8);
            }
        }
        CP_COMMIT();
    }

    // deferred quad reduction of l
    l0 += __shfl_xor_sync(~0u, l0, 1); l0 += __shfl_xor_sync(~0u, l0, 2);
    l1 += __shfl_xor_sync(~0u, l1, 1); l1 += __shfl_xor_sync(~0u, l1, 2);

    // ================= fused output projection epilogue =================
    __syncthreads();
    {
        __half (*wfs)[136] = (__half(*)[136])dyn;
        for (int idx = tid; idx < 128 * 32; idx += 128) {
            int oc = idx >> 5, u = idx & 31;
            float4 v = *(const float4*)(wf + (size_t)oc * NC + u * 4);
            __half2* d = (__half2*)&wfs[oc][u * 4];
            d[0] = __floats2half2_rn(v.x, v.y);
            d[1] = __floats2half2_rn(v.z, v.w);
        }
        if (tid < 128) bfs[tid] = bf[tid];
    }

    // pack normalized o into A-frags (rows = position, k = channel)
    float il0 = 1.f / l0, il1 = 1.f / l1;
    uint32_t AN[8][4];
#pragma unroll
    for (int kb = 0; kb < 8; kb++) {
        AN[kb][0] = packh2(O[2*kb][0]   * il0, O[2*kb][1]   * il0);
        AN[kb][1] = packh2(O[2*kb][2]   * il1, O[2*kb][3]   * il1);
        AN[kb][2] = packh2(O[2*kb+1][0] * il0, O[2*kb+1][1] * il0);
        AN[kb][3] = packh2(O[2*kb+1][2] * il1, O[2*kb+1][3] * il1);
    }
    __syncthreads();

    // R[pos][oc] = o_norm x wf^T
    {
        __half (*wfs)[136] = (__half(*)[136])dyn;
        float R[16][4];
#pragma unroll
        for (int i = 0; i < 16; i++) { R[i][0] = R[i][1] = R[i][2] = R[i][3] = 0.f; }
#pragma unroll
        for (int ob = 0; ob < 8; ob++) {
#pragma unroll
            for (int kb = 0; kb < 8; kb++) {
                uint32_t bfr[4];
                ldm_x4(bfr, sptr(&wfs[ob * 16 + vrow][kb * 16 + vcol]));
                mma16816(R[2 * ob],     AN[kb], bfr);
                mma16816(R[2 * ob + 1], AN[kb], bfr + 2);
            }
        }

        // out[oc][pos] = R + bias + x (residual)
        int row = i0 + warp * 16 + (lane >> 2);
        int c2 = (lane & 3) * 2;
        const float* xb = x + off;
        float* ob2 = out + off;
#pragma unroll
        for (int t = 0; t < 16; t++) {
            int oc = t * 8 + c2;
            size_t a0i = (size_t)oc * NN + row;
            size_t a1i = (size_t)(oc + 1) * NN + row;
            float b0 = bfs[oc], b1 = bfs[oc + 1];
            ob2[a0i]     = R[t][0] + b0 + xb[a0i];
            ob2[a1i]     = R[t][1] + b1 + xb[a1i];
            ob2[a0i + 8] = R[t][2] + b0 + xb[a0i + 8];
            ob2[a1i + 8] = R[t][3] + b1 + xb[a1i + 8];
        }
    }
}

// ---------------- launch ----------------
extern "C" void kernel_launch(void* const* d_in, const int* in_sizes, int n_in,
                              void* d_out, int out_size)
{
    (void)in_sizes; (void)n_in; (void)out_size;
    const float* x  = (const float*)d_in[0];
    const float* gw = (const float*)d_in[1];
    const float* gb = (const float*)d_in[2];
    const float* wq = (const float*)d_in[3];
    const float* bq = (const float*)d_in[4];
    const float* wk = (const float*)d_in[5];
    const float* bk = (const float*)d_in[6];
    const float* wv = (const float*)d_in[7];
    const float* bv = (const float*)d_in[8];
    const float* wf = (const float*)d_in[9];
    const float* bf = (const float*)d_in[10];
    float* out = (float*)d_out;

    static_assert(ATTN_SMEM == 110592, "smem size");
    cudaFuncSetAttribute(attn_kernel, cudaFuncAttributeMaxDynamicSharedMemorySize, ATTN_SMEM);

    gn_part_kernel<<<NB * NGROUPS * 4, 256>>>(x);
    gn_fin_kernel<<<1, 128>>>();
    qkv_kernel<<<dim3(32, NB), 256>>>(x, gw, gb, wq, bq, wk, bk, wv, bv);
    attn_kernel<<<dim3(64, NB), 128, ATTN_SMEM>>>(x, wf, bf, out);
}